// round 10
// baseline (speedup 1.0000x reference)
#include <cuda_runtime.h>
#include <cuda_fp16.h>
#include <math.h>
#include <stdint.h>

#define BB      4
#define LL      288
#define NNH     170
#define DDIM    128
#define WSZ     12
#define SHIFTSZ 6
#define HIDD    512
#define NWIN    24
#define MTOK    (BB * LL * NNH)   // 195840

// ---------------- scratch (fp16 activations) ----------------
__device__ __align__(256) __half g_xh[(size_t)MTOK * 128];
__device__ __align__(256) __half g_qkv[(size_t)MTOK * 384];
__device__ __align__(256) __half g_attn[(size_t)MTOK * 128];
__device__ __align__(256) __half g_x1h[(size_t)MTOK * 128];
// transposed weights [N][K], fp16
#define OFF_QKV  0
#define OFF_PROJ 49152
#define OFF_FC1  65536
#define OFF_FC2  131072
#define W_TOTAL  196608
__device__ __align__(256) __half g_w[W_TOTAL];

// ---------------- helpers ----------------
__device__ __forceinline__ uint32_t smem_u32(const void* p) {
    uint32_t a;
    asm("{ .reg .u64 t; cvta.to.shared.u64 t, %1; cvt.u32.u64 %0, t; }" : "=r"(a) : "l"(p));
    return a;
}
__device__ __forceinline__ void ldm4(uint32_t* r, uint32_t addr) {
    asm volatile("ldmatrix.sync.aligned.m8n8.x4.shared.b16 {%0,%1,%2,%3}, [%4];"
        : "=r"(r[0]), "=r"(r[1]), "=r"(r[2]), "=r"(r[3]) : "r"(addr));
}
__device__ __forceinline__ void mma16816(float* d, const uint32_t* a, uint32_t b0, uint32_t b1) {
    asm volatile("mma.sync.aligned.m16n8k16.row.col.f32.f16.f16.f32 "
        "{%0,%1,%2,%3}, {%4,%5,%6,%7}, {%8,%9}, {%0,%1,%2,%3};"
        : "+f"(d[0]), "+f"(d[1]), "+f"(d[2]), "+f"(d[3])
        : "r"(a[0]), "r"(a[1]), "r"(a[2]), "r"(a[3]), "r"(b0), "r"(b1));
}
#define CP16(dst, src) \
    asm volatile("cp.async.cg.shared.global [%0], [%1], 16;" :: "r"(dst), "l"(src) : "memory")
#define CPCOMMIT() asm volatile("cp.async.commit_group;" ::: "memory")

// streaming GEMM smem: stage = A 64x128B + B 128x128B, XOR-swizzled
#define A_T     8192
#define B_T     16384
#define STAGE   (A_T + B_T)            // 24576
#define EPI_B   32768
#define SM128   (2 * STAGE > EPI_B ? 2 * STAGE : EPI_B)   // 49152

// ---------------------------------------------------------------------------
// Streaming HMMA GEMM (round-8 proven): CTA 64x128, 8 warps 2m x 4n.
// MODE 0: A = g_xh;   epi = +bias -> g_qkv                      (K=128, N=384)
// MODE 1: A = g_attn; epi = unshift + LN1 + residual(x) -> x1h  (K=128, N=128)
// ---------------------------------------------------------------------------
template<int MODE, int K>
__global__ __launch_bounds__(256, 3)
void tc_gemm(int woff, const float* __restrict__ bias,
             const float* __restrict__ xin, const float* __restrict__ gamma,
             const float* __restrict__ beta)
{
    constexpr int NC = K / 64;
    constexpr int STAGES = 2;

    extern __shared__ __align__(1024) char smem[];
    const uint32_t sb = smem_u32(smem);
    const int tid = threadIdx.x;
    const int lane = tid & 31;
    const int wid = tid >> 5;
    const int wm = wid & 1;
    const int wn = wid >> 1;
    const int rowBlock = blockIdx.x * 64;
    const int colBlock = blockIdx.y * 128;

    const __half* asrc = (MODE == 0) ? g_xh : g_attn;
    const __half* wsrc = g_w + woff;

    const int lcc  = tid & 7;
    const int lrow = tid >> 3;
    const uint32_t swo = (uint32_t)(lcc ^ (lrow & 7)) * 16;

    float acc[2][4][4];
    #pragma unroll
    for (int mt = 0; mt < 2; mt++)
        #pragma unroll
        for (int nt = 0; nt < 4; nt++)
            #pragma unroll
            for (int e = 0; e < 4; e++) acc[mt][nt][e] = 0.f;

    auto load_stage = [&](int ch, int s) {
        const int k0 = ch * 64 + lcc * 8;
        const uint32_t sA = sb + (uint32_t)s * STAGE;
        #pragma unroll
        for (int j = 0; j < 2; j++) {
            const int row = lrow + 32 * j;
            CP16(sA + (uint32_t)row * 128 + swo, asrc + (size_t)(rowBlock + row) * K + k0);
        }
        #pragma unroll
        for (int j = 0; j < 4; j++) {
            const int row = lrow + 32 * j;
            CP16(sA + A_T + (uint32_t)row * 128 + swo, wsrc + (size_t)(colBlock + row) * K + k0);
        }
        CPCOMMIT();
    };

    const int lmRow = lane & 15;
    const int lmHalf = lane >> 4;

    load_stage(0, 0);
    for (int ch = 0; ch < NC; ch++) {
        if (ch + 1 < NC) {
            load_stage(ch + 1, (ch + 1) & 1);
            asm volatile("cp.async.wait_group 1;" ::: "memory");
        } else {
            asm volatile("cp.async.wait_group 0;" ::: "memory");
        }
        __syncthreads();

        const uint32_t sA = sb + (uint32_t)(ch % STAGES) * STAGE;
        const uint32_t sB = sA + A_T;
        #pragma unroll
        for (int kk = 0; kk < 4; kk++) {
            const int chk = kk * 2 + lmHalf;
            uint32_t af[2][4], bf[2][4];
            #pragma unroll
            for (int mt = 0; mt < 2; mt++) {
                const int rA = wm * 32 + mt * 16 + lmRow;
                ldm4(af[mt], sA + (uint32_t)rA * 128 + (uint32_t)((chk ^ (rA & 7)) * 16));
            }
            #pragma unroll
            for (int pt = 0; pt < 2; pt++) {
                const int rB = wn * 32 + pt * 16 + lmRow;
                ldm4(bf[pt], sB + (uint32_t)rB * 128 + (uint32_t)((chk ^ (rB & 7)) * 16));
            }
            #pragma unroll
            for (int mt = 0; mt < 2; mt++)
                #pragma unroll
                for (int nt = 0; nt < 4; nt++)
                    mma16816(acc[mt][nt], af[mt], bf[nt >> 1][nt & 1], bf[nt >> 1][(nt & 1) + 2]);
        }
        __syncthreads();
    }

    if (MODE == 0) {
        // direct +bias store to g_qkv
        #pragma unroll
        for (int mt = 0; mt < 2; mt++) {
            const int r0 = rowBlock + wm * 32 + mt * 16 + (lane >> 2);
            #pragma unroll
            for (int nt = 0; nt < 4; nt++) {
                const int c = colBlock + wn * 32 + nt * 8 + (lane & 3) * 2;
                const float b0 = bias[c], b1 = bias[c + 1];
                #pragma unroll
                for (int hh = 0; hh < 2; hh++) {
                    const int r = r0 + hh * 8;
                    float v0 = acc[mt][nt][hh * 2 + 0] + b0;
                    float v1 = acc[mt][nt][hh * 2 + 1] + b1;
                    *(__half2*)(g_qkv + (size_t)r * 384 + c) = __floats2half2_rn(v0, v1);
                }
            }
        }
        return;
    }

    // MODE 1: LN epilogue via permuted fp32 staging
    float* sf = (float*)smem;
    #pragma unroll
    for (int mt = 0; mt < 2; mt++) {
        #pragma unroll
        for (int nt = 0; nt < 4; nt++) {
            const int r0 = wm * 32 + mt * 16 + (lane >> 2);
            const int c  = wn * 32 + nt * 8 + (lane & 3) * 2;
            const int p0 = (c + 8 * r0) & 127;
            *(float2*)(sf + r0 * 128 + p0) = make_float2(acc[mt][nt][0], acc[mt][nt][1]);
            const int r1 = r0 + 8;
            const int p1 = (c + 8 * r1) & 127;
            *(float2*)(sf + r1 * 128 + p1) = make_float2(acc[mt][nt][2], acc[mt][nt][3]);
        }
    }
    __syncthreads();

    #pragma unroll 1
    for (int rr = 0; rr < 8; rr++) {
        const int lr = wid * 8 + rr;
        const int r  = rowBlock + lr;
        float4 v = *(float4*)(sf + lr * 128 + lane * 4);
        const int col = (lane * 4 - lr * 8) & 127;
        const float4 bv = *(const float4*)(bias + col);
        v.x += bv.x; v.y += bv.y; v.z += bv.z; v.w += bv.w;

        float s  = v.x + v.y + v.z + v.w;
        float s2 = v.x * v.x + v.y * v.y + v.z * v.z + v.w * v.w;
        #pragma unroll
        for (int off = 16; off > 0; off >>= 1) {
            s  += __shfl_xor_sync(0xFFFFFFFFu, s,  off);
            s2 += __shfl_xor_sync(0xFFFFFFFFu, s2, off);
        }
        const float mean = s * (1.f / 128.f);
        const float var  = fmaxf(s2 * (1.f / 128.f) - mean * mean, 0.f);
        const float rstd = rsqrtf(var + 1e-5f);

        const float4 gv = *(const float4*)(gamma + col);
        const float4 be = *(const float4*)(beta + col);

        int b = r / (NNH * LL), rem = r % (NNH * LL);
        int n = rem / LL, li = rem % LL;
        int lo_ = li - SHIFTSZ; if (lo_ < 0) lo_ += LL;
        const float4 res = *(const float4*)(xin + ((size_t)(b * LL + lo_) * NNH + n) * DDIM + col);
        float y0 = (v.x - mean) * rstd * gv.x + be.x + res.x;
        float y1 = (v.y - mean) * rstd * gv.y + be.y + res.y;
        float y2 = (v.z - mean) * rstd * gv.z + be.z + res.z;
        float y3 = (v.w - mean) * rstd * gv.w + be.w + res.w;
        __align__(8) __half hv[4];
        hv[0] = __float2half_rn(y0); hv[1] = __float2half_rn(y1);
        hv[2] = __float2half_rn(y2); hv[3] = __float2half_rn(y3);
        *(uint2*)(g_x1h + ((size_t)(b * NNH + n) * LL + lo_) * DDIM + col) = *(uint2*)hv;
    }
}

// ===========================================================================
// Fused MLP: h = GELU(x1 @ W1 + b1) kept in smem (64x512 fp16, chunk planes),
// then out = LN2(h @ W2 + b2) + residual(x1h), scattered to (B,L,N,D).
// Eliminates the 400MB g_h round-trip.
// smem: [0,16K) x1 A planes | [16K,80K) h planes (8 x 8KB) | [80K,112K) B dbuf
// ===========================================================================
#define FM_A    0
#define FM_H    16384
#define FM_B    81920
#define FM_SMEM 114688

__global__ __launch_bounds__(256, 2)
void tc_gemm_mlp(const float* __restrict__ bias1, const float* __restrict__ bias2,
                 float* __restrict__ outp, const float* __restrict__ gamma,
                 const float* __restrict__ beta)
{
    extern __shared__ __align__(1024) char smem[];
    const uint32_t sb = smem_u32(smem);
    const int tid = threadIdx.x;
    const int lane = tid & 31;
    const int wid = tid >> 5;
    const int wm = wid & 1;
    const int wn = wid >> 1;
    const int rowBlock = blockIdx.x * 64;

    const int lcc  = tid & 7;
    const int lrow = tid >> 3;
    const uint32_t swo = (uint32_t)(lcc ^ (lrow & 7)) * 16;

    const __half* w1 = g_w + OFF_FC1;   // [512][128]
    const __half* w2 = g_w + OFF_FC2;   // [128][512]

    // ---- load x1 A tile (2 chunk planes), one commit group ----
    #pragma unroll
    for (int ch = 0; ch < 2; ch++)
        #pragma unroll
        for (int j = 0; j < 2; j++) {
            const int row = lrow + 32 * j;
            CP16(sb + FM_A + (uint32_t)ch * 8192 + (uint32_t)row * 128 + swo,
                 g_x1h + (size_t)(rowBlock + row) * 128 + ch * 64 + lcc * 8);
        }
    CPCOMMIT();

    auto load_B1 = [&](int idx) {   // idx = nb*2 + ch
        const int nb = idx >> 1, ch = idx & 1;
        const uint32_t sB = sb + FM_B + (uint32_t)(idx & 1) * 16384;
        #pragma unroll
        for (int j = 0; j < 4; j++) {
            const int row = lrow + 32 * j;
            CP16(sB + (uint32_t)row * 128 + swo,
                 w1 + (size_t)(nb * 128 + row) * 128 + ch * 64 + lcc * 8);
        }
        CPCOMMIT();
    };
    auto load_B2 = [&](int ch2) {
        const uint32_t sB = sb + FM_B + (uint32_t)(ch2 & 1) * 16384;
        #pragma unroll
        for (int j = 0; j < 4; j++) {
            const int row = lrow + 32 * j;
            CP16(sB + (uint32_t)row * 128 + swo,
                 w2 + (size_t)row * 512 + ch2 * 64 + lcc * 8);
        }
        CPCOMMIT();
    };

    load_B1(0);
    load_B1(1);

    const int lmRow = lane & 15;
    const int lmHalf = lane >> 4;

    float acc[2][4][4];
    #pragma unroll
    for (int mt = 0; mt < 2; mt++)
        #pragma unroll
        for (int nt = 0; nt < 4; nt++)
            #pragma unroll
            for (int e = 0; e < 4; e++) acc[mt][nt][e] = 0.f;

    // ================= phase 1: fc1 + GELU -> smem h planes =================
    #pragma unroll
    for (int nb = 0; nb < 4; nb++) {
        #pragma unroll
        for (int ch = 0; ch < 2; ch++) {
            const int idx = nb * 2 + ch;
            if (idx + 1 < 8) asm volatile("cp.async.wait_group 1;" ::: "memory");
            else             asm volatile("cp.async.wait_group 0;" ::: "memory");
            __syncthreads();

            const uint32_t sA = sb + FM_A + (uint32_t)ch * 8192;
            const uint32_t sB = sb + FM_B + (uint32_t)(idx & 1) * 16384;
            #pragma unroll
            for (int kk = 0; kk < 4; kk++) {
                const int chk = kk * 2 + lmHalf;
                uint32_t af[2][4], bf[2][4];
                #pragma unroll
                for (int mt = 0; mt < 2; mt++) {
                    const int rA = wm * 32 + mt * 16 + lmRow;
                    ldm4(af[mt], sA + (uint32_t)rA * 128 + (uint32_t)((chk ^ (rA & 7)) * 16));
                }
                #pragma unroll
                for (int pt = 0; pt < 2; pt++) {
                    const int rB = wn * 32 + pt * 16 + lmRow;
                    ldm4(bf[pt], sB + (uint32_t)rB * 128 + (uint32_t)((chk ^ (rB & 7)) * 16));
                }
                #pragma unroll
                for (int mt = 0; mt < 2; mt++)
                    #pragma unroll
                    for (int nt = 0; nt < 4; nt++)
                        mma16816(acc[mt][nt], af[mt], bf[nt >> 1][nt & 1], bf[nt >> 1][(nt & 1) + 2]);
            }
            __syncthreads();
            if (idx + 2 < 8) load_B1(idx + 2);
        }

        // GELU + store to h planes (conflict-free swizzled half2 stores)
        #pragma unroll
        for (int mt = 0; mt < 2; mt++) {
            const int r0 = wm * 32 + mt * 16 + (lane >> 2);
            #pragma unroll
            for (int nt = 0; nt < 4; nt++) {
                const int c = nb * 128 + wn * 32 + nt * 8 + (lane & 3) * 2;
                const float b0 = bias1[c], b1 = bias1[c + 1];
                const int plane = c >> 6;
                const int cc = c & 63;
                #pragma unroll
                for (int hh = 0; hh < 2; hh++) {
                    const int row = r0 + hh * 8;
                    float v0 = acc[mt][nt][hh * 2 + 0] + b0;
                    float v1 = acc[mt][nt][hh * 2 + 1] + b1;
                    v0 *= normcdff(v0); v1 *= normcdff(v1);
                    const uint32_t off = FM_H + (uint32_t)plane * 8192 + (uint32_t)row * 128
                                       + (uint32_t)((((cc >> 3) ^ (row & 7)) << 4) + ((cc & 7) << 1));
                    *(__half2*)(smem + off) = __floats2half2_rn(v0, v1);
                    acc[mt][nt][hh * 2 + 0] = 0.f;
                    acc[mt][nt][hh * 2 + 1] = 0.f;
                }
            }
        }
    }

    // ================= phase 2: fc2 from smem h planes =================
    load_B2(0);
    load_B2(1);

    for (int ch2 = 0; ch2 < 8; ch2++) {
        if (ch2 + 1 < 8) asm volatile("cp.async.wait_group 1;" ::: "memory");
        else             asm volatile("cp.async.wait_group 0;" ::: "memory");
        __syncthreads();

        const uint32_t sA = sb + FM_H + (uint32_t)ch2 * 8192;
        const uint32_t sB = sb + FM_B + (uint32_t)(ch2 & 1) * 16384;
        #pragma unroll
        for (int kk = 0; kk < 4; kk++) {
            const int chk = kk * 2 + lmHalf;
            uint32_t af[2][4], bf[2][4];
            #pragma unroll
            for (int mt = 0; mt < 2; mt++) {
                const int rA = wm * 32 + mt * 16 + lmRow;
                ldm4(af[mt], sA + (uint32_t)rA * 128 + (uint32_t)((chk ^ (rA & 7)) * 16));
            }
            #pragma unroll
            for (int pt = 0; pt < 2; pt++) {
                const int rB = wn * 32 + pt * 16 + lmRow;
                ldm4(bf[pt], sB + (uint32_t)rB * 128 + (uint32_t)((chk ^ (rB & 7)) * 16));
            }
            #pragma unroll
            for (int mt = 0; mt < 2; mt++)
                #pragma unroll
                for (int nt = 0; nt < 4; nt++)
                    mma16816(acc[mt][nt], af[mt], bf[nt >> 1][nt & 1], bf[nt >> 1][(nt & 1) + 2]);
        }
        __syncthreads();
        if (ch2 + 2 < 8) load_B2(ch2 + 2);
    }

    // ---- LN2 + residual + scatter (staging buffer over B dbuf area) ----
    float* sf = (float*)(smem + FM_B);
    #pragma unroll
    for (int mt = 0; mt < 2; mt++) {
        #pragma unroll
        for (int nt = 0; nt < 4; nt++) {
            const int r0 = wm * 32 + mt * 16 + (lane >> 2);
            const int c  = wn * 32 + nt * 8 + (lane & 3) * 2;
            const int p0 = (c + 8 * r0) & 127;
            *(float2*)(sf + r0 * 128 + p0) = make_float2(acc[mt][nt][0], acc[mt][nt][1]);
            const int r1 = r0 + 8;
            const int p1 = (c + 8 * r1) & 127;
            *(float2*)(sf + r1 * 128 + p1) = make_float2(acc[mt][nt][2], acc[mt][nt][3]);
        }
    }
    __syncthreads();

    #pragma unroll 1
    for (int rr = 0; rr < 8; rr++) {
        const int lr = wid * 8 + rr;
        const int r  = rowBlock + lr;
        float4 v = *(float4*)(sf + lr * 128 + lane * 4);
        const int col = (lane * 4 - lr * 8) & 127;
        const float4 bv = *(const float4*)(bias2 + col);
        v.x += bv.x; v.y += bv.y; v.z += bv.z; v.w += bv.w;

        float s  = v.x + v.y + v.z + v.w;
        float s2 = v.x * v.x + v.y * v.y + v.z * v.z + v.w * v.w;
        #pragma unroll
        for (int off = 16; off > 0; off >>= 1) {
            s  += __shfl_xor_sync(0xFFFFFFFFu, s,  off);
            s2 += __shfl_xor_sync(0xFFFFFFFFu, s2, off);
        }
        const float mean = s * (1.f / 128.f);
        const float var  = fmaxf(s2 * (1.f / 128.f) - mean * mean, 0.f);
        const float rstd = rsqrtf(var + 1e-5f);

        const float4 gv = *(const float4*)(gamma + col);
        const float4 be = *(const float4*)(beta + col);

        int b = r / (NNH * LL), rem = r % (NNH * LL);
        int n = rem / LL, li = rem % LL;

        const uint2 rh = *(const uint2*)(g_x1h + (size_t)r * 128 + col);
        const __half* rp = (const __half*)&rh;
        float4 o;
        o.x = (v.x - mean) * rstd * gv.x + be.x + __half2float(rp[0]);
        o.y = (v.y - mean) * rstd * gv.y + be.y + __half2float(rp[1]);
        o.z = (v.z - mean) * rstd * gv.z + be.z + __half2float(rp[2]);
        o.w = (v.w - mean) * rstd * gv.w + be.w + __half2float(rp[3]);
        *(float4*)(outp + ((size_t)(b * LL + li) * NNH + n) * DDIM + col) = o;
    }
}

// ---------------------------------------------------------------------------
// prep_x: x (B,L,N,D fp32) -> g_xh (b,n,ls) fp16 with shift fused.
// ---------------------------------------------------------------------------
__global__ __launch_bounds__(256)
void prep_x(const float* __restrict__ x)
{
    const int row = blockIdx.x * 8 + (threadIdx.x >> 5);
    const int lane = threadIdx.x & 31;
    int b = row / (NNH * LL), rem = row % (NNH * LL);
    int n = rem / LL, ls = rem % LL;
    int l = ls - SHIFTSZ; if (l < 0) l += LL;
    const float4 v = *(const float4*)(x + ((size_t)(b * LL + l) * NNH + n) * DDIM + lane * 4);
    __align__(8) __half hv[4];
    hv[0] = __float2half_rn(v.x); hv[1] = __float2half_rn(v.y);
    hv[2] = __float2half_rn(v.z); hv[3] = __float2half_rn(v.w);
    *(uint2*)(g_xh + (size_t)row * 128 + lane * 4) = *(uint2*)hv;
}

// ---------------------------------------------------------------------------
// Weight prep: fp32 [K][N] -> transposed fp16 [N][K]
// ---------------------------------------------------------------------------
__global__ void prep_w(const float* __restrict__ qkv_w, const float* __restrict__ proj_w,
                       const float* __restrict__ fc1_w, const float* __restrict__ fc2_w)
{
    int idx = blockIdx.x * 256 + threadIdx.x;
    if (idx >= W_TOTAL) return;
    const float* src; int K, N, base;
    if (idx < OFF_PROJ)      { src = qkv_w;  K = 128; N = 384; base = OFF_QKV;  }
    else if (idx < OFF_FC1)  { src = proj_w; K = 128; N = 128; base = OFF_PROJ; }
    else if (idx < OFF_FC2)  { src = fc1_w;  K = 128; N = 512; base = OFF_FC1;  }
    else                     { src = fc2_w;  K = 512; N = 128; base = OFF_FC2;  }
    int local = idx - base;
    int nn = local / K, kk = local % K;
    g_w[idx] = __float2half_rn(src[(size_t)kk * N + nn]);
}

// ---------------------------------------------------------------------------
// Windowed attention: 192 threads = 2 windows x (head, row), uint4 smem I/O.
// ---------------------------------------------------------------------------
__global__ __launch_bounds__(192)
void attn_kernel()
{
    __shared__ __half s[2][12 * 384];

    const int blk = blockIdx.x;
    const int wp  = blk % (NWIN / 2);
    const int rem = blk / (NWIN / 2);
    const int n   = rem % NNH;
    const int b   = rem / NNH;
    const int half_id = threadIdx.x / 96;
    const int tid = threadIdx.x % 96;
    const int w   = wp * 2 + half_id;
    const size_t base = (size_t)(b * NNH + n) * LL + w * WSZ;

    __half* sp = s[half_id];
    const uint4* src = (const uint4*)(g_qkv + base * 384);
    uint4* dst = (uint4*)sp;
    #pragma unroll
    for (int v = 0; v < 6; v++)
        dst[tid + v * 96] = src[tid + v * 96];
    __syncthreads();

    const int h = tid / 12;
    const int i = tid % 12;
    const bool gi = (i < SHIFTSZ);

    float q[16];
    {
        uint4 qa = *(const uint4*)(sp + i * 384 + h * 16);
        uint4 qb = *(const uint4*)(sp + i * 384 + h * 16 + 8);
        const __half2* pa = (const __half2*)&qa;
        const __half2* pb = (const __half2*)&qb;
        #pragma unroll
        for (int e = 0; e < 4; e++) {
            float2 fa = __half22float2(pa[e]);
            float2 fb = __half22float2(pb[e]);
            q[e * 2] = fa.x; q[e * 2 + 1] = fa.y;
            q[8 + e * 2] = fb.x; q[8 + e * 2 + 1] = fb.y;
        }
    }

    float sc[12];
    float mx = -1e30f;
    #pragma unroll
    for (int j = 0; j < 12; j++) {
        uint4 ka = *(const uint4*)(sp + j * 384 + 128 + h * 16);
        uint4 kb = *(const uint4*)(sp + j * 384 + 128 + h * 16 + 8);
        const __half2* pa = (const __half2*)&ka;
        const __half2* pb = (const __half2*)&kb;
        float a = 0.f;
        #pragma unroll
        for (int e = 0; e < 4; e++) {
            float2 fa = __half22float2(pa[e]);
            float2 fb = __half22float2(pb[e]);
            a += q[e * 2] * fa.x + q[e * 2 + 1] * fa.y;
            a += q[8 + e * 2] * fb.x + q[8 + e * 2 + 1] * fb.y;
        }
        a *= 0.25f;
        if (w == 0 && (gi != (j < SHIFTSZ))) a -= 100.f;
        sc[j] = a;
        mx = fmaxf(mx, a);
    }
    float den = 0.f;
    #pragma unroll
    for (int j = 0; j < 12; j++) { sc[j] = __expf(sc[j] - mx); den += sc[j]; }
    const float inv = 1.f / den;

    float o[16];
    #pragma unroll
    for (int d = 0; d < 16; d++) o[d] = 0.f;
    #pragma unroll
    for (int j = 0; j < 12; j++) {
        const float p = sc[j] * inv;
        uint4 va = *(const uint4*)(sp + j * 384 + 256 + h * 16);
        uint4 vb = *(const uint4*)(sp + j * 384 + 256 + h * 16 + 8);
        const __half2* pa = (const __half2*)&va;
        const __half2* pb = (const __half2*)&vb;
        #pragma unroll
        for (int e = 0; e < 4; e++) {
            float2 fa = __half22float2(pa[e]);
            float2 fb = __half22float2(pb[e]);
            o[e * 2]     += p * fa.x; o[e * 2 + 1] += p * fa.y;
            o[8 + e * 2] += p * fb.x; o[8 + e * 2 + 1] += p * fb.y;
        }
    }

    __align__(16) __half hv[16];
    #pragma unroll
    for (int d = 0; d < 16; d++) hv[d] = __float2half_rn(o[d]);
    __half* dsto = g_attn + (base + i) * 128 + h * 16;
    *(uint4*)(dsto)     = *(uint4*)(hv);
    *(uint4*)(dsto + 8) = *(uint4*)(hv + 8);
}

// ---------------------------------------------------------------------------
extern "C" void kernel_launch(void* const* d_in, const int* in_sizes, int n_in,
                              void* d_out, int out_size)
{
    const float* x      = (const float*)d_in[0];
    const float* qkv_w  = (const float*)d_in[1];
    const float* qkv_b  = (const float*)d_in[2];
    const float* proj_w = (const float*)d_in[3];
    const float* proj_b = (const float*)d_in[4];
    const float* fc1_w  = (const float*)d_in[5];
    const float* fc1_b  = (const float*)d_in[6];
    const float* fc2_w  = (const float*)d_in[7];
    const float* fc2_b  = (const float*)d_in[8];
    const float* g1     = (const float*)d_in[9];
    const float* b1     = (const float*)d_in[10];
    const float* g2     = (const float*)d_in[11];
    const float* b2     = (const float*)d_in[12];
    float* out = (float*)d_out;

    static bool attr_done = false;
    if (!attr_done) {
        cudaFuncSetAttribute(tc_gemm<0, 128>, cudaFuncAttributeMaxDynamicSharedMemorySize, SM128);
        cudaFuncSetAttribute(tc_gemm<1, 128>, cudaFuncAttributeMaxDynamicSharedMemorySize, SM128);
        cudaFuncSetAttribute(tc_gemm_mlp,     cudaFuncAttributeMaxDynamicSharedMemorySize, FM_SMEM);
        attr_done = true;
    }

    const int MB = MTOK / 64; // 3060

    prep_w<<<(W_TOTAL + 255) / 256, 256>>>(qkv_w, proj_w, fc1_w, fc2_w);
    prep_x<<<MTOK / 8, 256>>>(x);
    // 1) QKV projection (streaming, 3 column blocks)
    tc_gemm<0, 128><<<dim3(MB, 3), 256, SM128>>>(OFF_QKV, qkv_b, nullptr, nullptr, nullptr);
    // 2) windowed attention
    attn_kernel<<<BB * NNH * (NWIN / 2), 192>>>();
    // 3) proj + unshift + LN1 + residual(x)
    tc_gemm<1, 128><<<dim3(MB, 1), 256, SM128>>>(OFF_PROJ, proj_b, x, g1, b1);
    // 4+5) fused MLP: fc1 + GELU (smem-resident h) + fc2 + LN2 + residual + scatter
    tc_gemm_mlp<<<MB, 256, FM_SMEM>>>(fc1_b, fc2_b, out, g2, b2);
}

// round 11
// speedup vs baseline: 1.5965x; 1.5965x over previous
#include <cuda_runtime.h>
#include <cuda_fp16.h>
#include <math.h>
#include <stdint.h>

#define BB      4
#define LL      288
#define NNH     170
#define DDIM    128
#define WSZ     12
#define SHIFTSZ 6
#define HIDD    512
#define NWIN    24
#define MTOK    (BB * LL * NNH)   // 195840

// ---------------- scratch (fp16 activations) ----------------
__device__ __align__(256) __half g_xh[(size_t)MTOK * 128];
__device__ __align__(256) __half g_qkv[(size_t)MTOK * 384];
__device__ __align__(256) __half g_attn[(size_t)MTOK * 128];
__device__ __align__(256) __half g_x1h[(size_t)MTOK * 128];
__device__ __align__(256) __half g_h[(size_t)MTOK * 512];
// transposed weights [N][K], fp16
#define OFF_QKV  0
#define OFF_PROJ 49152
#define OFF_FC1  65536
#define OFF_FC2  131072
#define W_TOTAL  196608
__device__ __align__(256) __half g_w[W_TOTAL];

// ---------------- helpers ----------------
__device__ __forceinline__ uint32_t smem_u32(const void* p) {
    uint32_t a;
    asm("{ .reg .u64 t; cvta.to.shared.u64 t, %1; cvt.u32.u64 %0, t; }" : "=r"(a) : "l"(p));
    return a;
}
__device__ __forceinline__ void ldm4(uint32_t* r, uint32_t addr) {
    asm volatile("ldmatrix.sync.aligned.m8n8.x4.shared.b16 {%0,%1,%2,%3}, [%4];"
        : "=r"(r[0]), "=r"(r[1]), "=r"(r[2]), "=r"(r[3]) : "r"(addr));
}
__device__ __forceinline__ void mma16816(float* d, const uint32_t* a, uint32_t b0, uint32_t b1) {
    asm volatile("mma.sync.aligned.m16n8k16.row.col.f32.f16.f16.f32 "
        "{%0,%1,%2,%3}, {%4,%5,%6,%7}, {%8,%9}, {%0,%1,%2,%3};"
        : "+f"(d[0]), "+f"(d[1]), "+f"(d[2]), "+f"(d[3])
        : "r"(a[0]), "r"(a[1]), "r"(a[2]), "r"(a[3]), "r"(b0), "r"(b1));
}
#define CP16(dst, src) \
    asm volatile("cp.async.cg.shared.global [%0], [%1], 16;" :: "r"(dst), "l"(src) : "memory")
#define CPCOMMIT() asm volatile("cp.async.commit_group;" ::: "memory")

// stage: A 64x128B (swizzled) + B 128x128B (swizzled)
#define A_T     8192
#define B_T     16384
#define STAGE   (A_T + B_T)            // 24576
#define EPI_B   32768                  // 64 x 128 fp32 (permuted)
#define SM128   (2 * STAGE > EPI_B ? 2 * STAGE : EPI_B)   // 49152
#define SM512   (3 * STAGE)                                // 73728

// ---------------------------------------------------------------------------
// Streaming HMMA GEMM (round-8 proven): CTA 64x128, 8 warps 2m x 4n.
// MODE 0: A = g_xh;   epi = +bias -> g_qkv                      (K=128, N=384)
// MODE 1: A = g_attn; epi = unshift + LN1 + residual(x) -> x1h  (K=128, N=128)
// MODE 2: A = g_x1h;  epi = GELU -> g_h                          (K=128, N=512)
// MODE 3: A = g_h;    epi = LN2 + residual(x1h) -> out fp32      (K=512, N=128)
// ---------------------------------------------------------------------------
template<int MODE, int K>
__global__ __launch_bounds__(256, 3)
void tc_gemm(int woff, const float* __restrict__ bias, float* __restrict__ outp,
             const float* __restrict__ xin, const float* __restrict__ gamma,
             const float* __restrict__ beta)
{
    constexpr int NC = K / 64;
    constexpr int STAGES = (NC >= 3) ? 3 : 2;

    extern __shared__ __align__(1024) char smem[];
    const uint32_t sb = smem_u32(smem);
    const int tid = threadIdx.x;
    const int lane = tid & 31;
    const int wid = tid >> 5;
    const int wm = wid & 1;
    const int wn = wid >> 1;
    const int rowBlock = blockIdx.x * 64;
    const int colBlock = blockIdx.y * 128;

    const __half* asrc;
    if (MODE == 0) asrc = g_xh;
    else if (MODE == 1) asrc = g_attn;
    else if (MODE == 2) asrc = g_x1h;
    else asrc = g_h;
    const __half* wsrc = g_w + woff;

    const int lcc  = tid & 7;
    const int lrow = tid >> 3;
    const uint32_t swo = (uint32_t)(lcc ^ (lrow & 7)) * 16;

    float acc[2][4][4];
    #pragma unroll
    for (int mt = 0; mt < 2; mt++)
        #pragma unroll
        for (int nt = 0; nt < 4; nt++)
            #pragma unroll
            for (int e = 0; e < 4; e++) acc[mt][nt][e] = 0.f;

    auto load_stage = [&](int ch, int s) {
        const int k0 = ch * 64 + lcc * 8;
        const uint32_t sA = sb + (uint32_t)s * STAGE;
        #pragma unroll
        for (int j = 0; j < 2; j++) {
            const int row = lrow + 32 * j;
            CP16(sA + (uint32_t)row * 128 + swo, asrc + (size_t)(rowBlock + row) * K + k0);
        }
        #pragma unroll
        for (int j = 0; j < 4; j++) {
            const int row = lrow + 32 * j;
            CP16(sA + A_T + (uint32_t)row * 128 + swo, wsrc + (size_t)(colBlock + row) * K + k0);
        }
        CPCOMMIT();
    };

    const int lmRow = lane & 15;
    const int lmHalf = lane >> 4;

    load_stage(0, 0);
    if (STAGES >= 3 && NC >= 2) load_stage(1, 1);

    for (int ch = 0; ch < NC; ch++) {
        const int nxt = ch + STAGES - 1;
        if (nxt < NC) {
            load_stage(nxt, nxt % STAGES);
            if (STAGES == 3) asm volatile("cp.async.wait_group 2;" ::: "memory");
            else             asm volatile("cp.async.wait_group 1;" ::: "memory");
        } else {
            if (STAGES == 3 && ch < NC - 1) asm volatile("cp.async.wait_group 1;" ::: "memory");
            else                             asm volatile("cp.async.wait_group 0;" ::: "memory");
        }
        __syncthreads();

        const uint32_t sA = sb + (uint32_t)(ch % STAGES) * STAGE;
        const uint32_t sB = sA + A_T;
        #pragma unroll
        for (int kk = 0; kk < 4; kk++) {
            const int chk = kk * 2 + lmHalf;
            uint32_t af[2][4], bf[2][4];
            #pragma unroll
            for (int mt = 0; mt < 2; mt++) {
                const int rA = wm * 32 + mt * 16 + lmRow;
                ldm4(af[mt], sA + (uint32_t)rA * 128 + (uint32_t)((chk ^ (rA & 7)) * 16));
            }
            #pragma unroll
            for (int pt = 0; pt < 2; pt++) {
                const int rB = wn * 32 + pt * 16 + lmRow;
                ldm4(bf[pt], sB + (uint32_t)rB * 128 + (uint32_t)((chk ^ (rB & 7)) * 16));
            }
            #pragma unroll
            for (int mt = 0; mt < 2; mt++)
                #pragma unroll
                for (int nt = 0; nt < 4; nt++)
                    mma16816(acc[mt][nt], af[mt], bf[nt >> 1][nt & 1], bf[nt >> 1][(nt & 1) + 2]);
        }
        __syncthreads();
    }

    if (MODE == 0 || MODE == 2) {
        const int ld = (MODE == 0) ? 384 : 512;
        __half* base = (MODE == 0) ? g_qkv : g_h;
        #pragma unroll
        for (int mt = 0; mt < 2; mt++) {
            const int r0 = rowBlock + wm * 32 + mt * 16 + (lane >> 2);
            #pragma unroll
            for (int nt = 0; nt < 4; nt++) {
                const int c = colBlock + wn * 32 + nt * 8 + (lane & 3) * 2;
                const float b0 = bias[c], b1 = bias[c + 1];
                #pragma unroll
                for (int hh = 0; hh < 2; hh++) {
                    const int r = r0 + hh * 8;
                    float v0 = acc[mt][nt][hh * 2 + 0] + b0;
                    float v1 = acc[mt][nt][hh * 2 + 1] + b1;
                    if (MODE == 2) { v0 *= normcdff(v0); v1 *= normcdff(v1); }
                    *(__half2*)(base + (size_t)r * ld + c) = __floats2half2_rn(v0, v1);
                }
            }
        }
        return;
    }

    // LN modes (1 and 3): permuted fp32 staging + warp-per-row epilogue
    float* sf = (float*)smem;
    #pragma unroll
    for (int mt = 0; mt < 2; mt++) {
        #pragma unroll
        for (int nt = 0; nt < 4; nt++) {
            const int r0 = wm * 32 + mt * 16 + (lane >> 2);
            const int c  = wn * 32 + nt * 8 + (lane & 3) * 2;
            const int p0 = (c + 8 * r0) & 127;
            *(float2*)(sf + r0 * 128 + p0) = make_float2(acc[mt][nt][0], acc[mt][nt][1]);
            const int r1 = r0 + 8;
            const int p1 = (c + 8 * r1) & 127;
            *(float2*)(sf + r1 * 128 + p1) = make_float2(acc[mt][nt][2], acc[mt][nt][3]);
        }
    }
    __syncthreads();

    #pragma unroll 1
    for (int rr = 0; rr < 8; rr++) {
        const int lr = wid * 8 + rr;
        const int r  = rowBlock + lr;
        float4 v = *(float4*)(sf + lr * 128 + lane * 4);
        const int col = (lane * 4 - lr * 8) & 127;
        const float4 bv = *(const float4*)(bias + col);
        v.x += bv.x; v.y += bv.y; v.z += bv.z; v.w += bv.w;

        float s  = v.x + v.y + v.z + v.w;
        float s2 = v.x * v.x + v.y * v.y + v.z * v.z + v.w * v.w;
        #pragma unroll
        for (int off = 16; off > 0; off >>= 1) {
            s  += __shfl_xor_sync(0xFFFFFFFFu, s,  off);
            s2 += __shfl_xor_sync(0xFFFFFFFFu, s2, off);
        }
        const float mean = s * (1.f / 128.f);
        const float var  = fmaxf(s2 * (1.f / 128.f) - mean * mean, 0.f);
        const float rstd = rsqrtf(var + 1e-5f);

        const float4 gv = *(const float4*)(gamma + col);
        const float4 be = *(const float4*)(beta + col);

        int b = r / (NNH * LL), rem = r % (NNH * LL);
        int n = rem / LL, li = rem % LL;

        if (MODE == 1) {
            int lo_ = li - SHIFTSZ; if (lo_ < 0) lo_ += LL;
            const float4 res = *(const float4*)(xin + ((size_t)(b * LL + lo_) * NNH + n) * DDIM + col);
            float y0 = (v.x - mean) * rstd * gv.x + be.x + res.x;
            float y1 = (v.y - mean) * rstd * gv.y + be.y + res.y;
            float y2 = (v.z - mean) * rstd * gv.z + be.z + res.z;
            float y3 = (v.w - mean) * rstd * gv.w + be.w + res.w;
            __align__(8) __half hv[4];
            hv[0] = __float2half_rn(y0); hv[1] = __float2half_rn(y1);
            hv[2] = __float2half_rn(y2); hv[3] = __float2half_rn(y3);
            *(uint2*)(g_x1h + ((size_t)(b * NNH + n) * LL + lo_) * DDIM + col) = *(uint2*)hv;
        } else {
            const uint2 rh = *(const uint2*)(g_x1h + (size_t)r * 128 + col);
            const __half* rp = (const __half*)&rh;
            float4 o;
            o.x = (v.x - mean) * rstd * gv.x + be.x + __half2float(rp[0]);
            o.y = (v.y - mean) * rstd * gv.y + be.y + __half2float(rp[1]);
            o.z = (v.z - mean) * rstd * gv.z + be.z + __half2float(rp[2]);
            o.w = (v.w - mean) * rstd * gv.w + be.w + __half2float(rp[3]);
            *(float4*)(outp + ((size_t)(b * LL + li) * NNH + n) * DDIM + col) = o;
        }
    }
}

// ---------------------------------------------------------------------------
// prep_x: x (B,L,N,D fp32) -> g_xh (b,n,ls) fp16 with shift fused.
// ---------------------------------------------------------------------------
__global__ __launch_bounds__(256)
void prep_x(const float* __restrict__ x)
{
    const int row = blockIdx.x * 8 + (threadIdx.x >> 5);
    const int lane = threadIdx.x & 31;
    int b = row / (NNH * LL), rem = row % (NNH * LL);
    int n = rem / LL, ls = rem % LL;
    int l = ls - SHIFTSZ; if (l < 0) l += LL;
    const float4 v = *(const float4*)(x + ((size_t)(b * LL + l) * NNH + n) * DDIM + lane * 4);
    __align__(8) __half hv[4];
    hv[0] = __float2half_rn(v.x); hv[1] = __float2half_rn(v.y);
    hv[2] = __float2half_rn(v.z); hv[3] = __float2half_rn(v.w);
    *(uint2*)(g_xh + (size_t)row * 128 + lane * 4) = *(uint2*)hv;
}

// ---------------------------------------------------------------------------
// Weight prep: fp32 [K][N] -> transposed fp16 [N][K]
// ---------------------------------------------------------------------------
__global__ void prep_w(const float* __restrict__ qkv_w, const float* __restrict__ proj_w,
                       const float* __restrict__ fc1_w, const float* __restrict__ fc2_w)
{
    int idx = blockIdx.x * 256 + threadIdx.x;
    if (idx >= W_TOTAL) return;
    const float* src; int K, N, base;
    if (idx < OFF_PROJ)      { src = qkv_w;  K = 128; N = 384; base = OFF_QKV;  }
    else if (idx < OFF_FC1)  { src = proj_w; K = 128; N = 128; base = OFF_PROJ; }
    else if (idx < OFF_FC2)  { src = fc1_w;  K = 128; N = 512; base = OFF_FC1;  }
    else                     { src = fc2_w;  K = 512; N = 128; base = OFF_FC2;  }
    int local = idx - base;
    int nn = local / K, kk = local % K;
    g_w[idx] = __float2half_rn(src[(size_t)kk * N + nn]);
}

// ---------------------------------------------------------------------------
// Windowed attention: 192 threads = 2 windows x (head, row).
// Staging converts fp16 -> fp32 ONCE per element; compute uses LDS.128 float4
// with zero per-use conversions (was 12 redundant converts per element).
// ---------------------------------------------------------------------------
__global__ __launch_bounds__(192)
void attn_kernel()
{
    __shared__ float s[2][12 * 384];   // 36 KB

    const int blk = blockIdx.x;
    const int wp  = blk % (NWIN / 2);
    const int rem = blk / (NWIN / 2);
    const int n   = rem % NNH;
    const int b   = rem / NNH;
    const int half_id = threadIdx.x / 96;
    const int tid = threadIdx.x % 96;
    const int w   = wp * 2 + half_id;
    const size_t base = (size_t)(b * NNH + n) * LL + w * WSZ;

    // stage: 576 uint4 per window; convert each element once to fp32
    float* sp = s[half_id];
    const uint4* src = (const uint4*)(g_qkv + base * 384);
    #pragma unroll
    for (int v = 0; v < 6; v++) {
        const int idx = tid + v * 96;
        uint4 hv = src[idx];
        const __half2* ph = (const __half2*)&hv;
        float2 f0 = __half22float2(ph[0]);
        float2 f1 = __half22float2(ph[1]);
        float2 f2 = __half22float2(ph[2]);
        float2 f3 = __half22float2(ph[3]);
        *(float4*)(sp + idx * 8)     = make_float4(f0.x, f0.y, f1.x, f1.y);
        *(float4*)(sp + idx * 8 + 4) = make_float4(f2.x, f2.y, f3.x, f3.y);
    }
    __syncthreads();

    const int h = tid / 12;
    const int i = tid % 12;
    const bool gi = (i < SHIFTSZ);

    // q -> registers (4x LDS.128)
    float q[16];
    #pragma unroll
    for (int e = 0; e < 4; e++)
        *(float4*)(q + e * 4) = *(const float4*)(sp + i * 384 + h * 16 + e * 4);

    float sc[12];
    float mx = -1e30f;
    #pragma unroll
    for (int j = 0; j < 12; j++) {
        const float* kp = sp + j * 384 + 128 + h * 16;
        float4 k0 = *(const float4*)(kp);
        float4 k1 = *(const float4*)(kp + 4);
        float4 k2 = *(const float4*)(kp + 8);
        float4 k3 = *(const float4*)(kp + 12);
        float a = q[0]*k0.x + q[1]*k0.y + q[2]*k0.z + q[3]*k0.w
                + q[4]*k1.x + q[5]*k1.y + q[6]*k1.z + q[7]*k1.w
                + q[8]*k2.x + q[9]*k2.y + q[10]*k2.z + q[11]*k2.w
                + q[12]*k3.x + q[13]*k3.y + q[14]*k3.z + q[15]*k3.w;
        a *= 0.25f;
        if (w == 0 && (gi != (j < SHIFTSZ))) a -= 100.f;
        sc[j] = a;
        mx = fmaxf(mx, a);
    }
    float den = 0.f;
    #pragma unroll
    for (int j = 0; j < 12; j++) { sc[j] = __expf(sc[j] - mx); den += sc[j]; }
    const float inv = 1.f / den;

    float o[16];
    #pragma unroll
    for (int d = 0; d < 16; d++) o[d] = 0.f;
    #pragma unroll
    for (int j = 0; j < 12; j++) {
        const float p = sc[j] * inv;
        const float* vp = sp + j * 384 + 256 + h * 16;
        float4 v0 = *(const float4*)(vp);
        float4 v1 = *(const float4*)(vp + 4);
        float4 v2 = *(const float4*)(vp + 8);
        float4 v3 = *(const float4*)(vp + 12);
        o[0] += p*v0.x; o[1] += p*v0.y; o[2]  += p*v0.z; o[3]  += p*v0.w;
        o[4] += p*v1.x; o[5] += p*v1.y; o[6]  += p*v1.z; o[7]  += p*v1.w;
        o[8] += p*v2.x; o[9] += p*v2.y; o[10] += p*v2.z; o[11] += p*v2.w;
        o[12] += p*v3.x; o[13] += p*v3.y; o[14] += p*v3.z; o[15] += p*v3.w;
    }

    __align__(16) __half hv[16];
    #pragma unroll
    for (int d = 0; d < 8; d++)
        *(__half2*)(hv + d * 2) = __floats2half2_rn(o[d * 2], o[d * 2 + 1]);
    __half* dsto = g_attn + (base + i) * 128 + h * 16;
    *(uint4*)(dsto)     = *(uint4*)(hv);
    *(uint4*)(dsto + 8) = *(uint4*)(hv + 8);
}

// ---------------------------------------------------------------------------
extern "C" void kernel_launch(void* const* d_in, const int* in_sizes, int n_in,
                              void* d_out, int out_size)
{
    const float* x      = (const float*)d_in[0];
    const float* qkv_w  = (const float*)d_in[1];
    const float* qkv_b  = (const float*)d_in[2];
    const float* proj_w = (const float*)d_in[3];
    const float* proj_b = (const float*)d_in[4];
    const float* fc1_w  = (const float*)d_in[5];
    const float* fc1_b  = (const float*)d_in[6];
    const float* fc2_w  = (const float*)d_in[7];
    const float* fc2_b  = (const float*)d_in[8];
    const float* g1     = (const float*)d_in[9];
    const float* b1     = (const float*)d_in[10];
    const float* g2     = (const float*)d_in[11];
    const float* b2     = (const float*)d_in[12];
    float* out = (float*)d_out;

    static bool attr_done = false;
    if (!attr_done) {
        cudaFuncSetAttribute(tc_gemm<0, 128>, cudaFuncAttributeMaxDynamicSharedMemorySize, SM128);
        cudaFuncSetAttribute(tc_gemm<1, 128>, cudaFuncAttributeMaxDynamicSharedMemorySize, SM128);
        cudaFuncSetAttribute(tc_gemm<2, 128>, cudaFuncAttributeMaxDynamicSharedMemorySize, SM128);
        cudaFuncSetAttribute(tc_gemm<3, 512>, cudaFuncAttributeMaxDynamicSharedMemorySize, SM512);
        attr_done = true;
    }

    const int MB = MTOK / 64; // 3060

    // 0) weight transpose to fp16 [N][K]; x gather/shift to fp16
    prep_w<<<(W_TOTAL + 255) / 256, 256>>>(qkv_w, proj_w, fc1_w, fc2_w);
    prep_x<<<MTOK / 8, 256>>>(x);
    // 1) QKV projection (streaming, 3 column blocks)
    tc_gemm<0, 128><<<dim3(MB, 3), 256, SM128>>>(OFF_QKV, qkv_b, nullptr, nullptr, nullptr, nullptr);
    // 2) windowed attention (2 windows per block, fp32 smem tiles)
    attn_kernel<<<BB * NNH * (NWIN / 2), 192>>>();
    // 3) proj + unshift + LN1 + residual(x)
    tc_gemm<1, 128><<<dim3(MB, 1), 256, SM128>>>(OFF_PROJ, proj_b, nullptr, x, g1, b1);
    // 4) fc1 + GELU
    tc_gemm<2, 128><<<dim3(MB, 4), 256, SM128>>>(OFF_FC1, fc1_b, nullptr, nullptr, nullptr, nullptr);
    // 5) fc2 + LN2 + residual(x1h) + scatter to (B,L,N,D)
    tc_gemm<3, 512><<<dim3(MB, 1), 256, SM512>>>(OFF_FC2, fc2_b, out, nullptr, g2, b2);
}

// round 12
// speedup vs baseline: 1.6367x; 1.0252x over previous
#include <cuda_runtime.h>
#include <cuda_fp16.h>
#include <math.h>
#include <stdint.h>

#define BB      4
#define LL      288
#define NNH     170
#define DDIM    128
#define WSZ     12
#define SHIFTSZ 6
#define HIDD    512
#define NWIN    24
#define MTOK    (BB * LL * NNH)   // 195840

// ---------------- scratch (fp16 activations) ----------------
__device__ __align__(256) __half g_xh[(size_t)MTOK * 128];
__device__ __align__(256) __half g_qkv[(size_t)MTOK * 384];
__device__ __align__(256) __half g_attn[(size_t)MTOK * 128];
__device__ __align__(256) __half g_x1h[(size_t)MTOK * 128];
__device__ __align__(256) __half g_h[(size_t)MTOK * 512];
// transposed weights [N][K], fp16
#define OFF_QKV  0
#define OFF_PROJ 49152
#define OFF_FC1  65536
#define OFF_FC2  131072
#define W_TOTAL  196608
__device__ __align__(256) __half g_w[W_TOTAL];

// ---------------- helpers ----------------
__device__ __forceinline__ uint32_t smem_u32(const void* p) {
    uint32_t a;
    asm("{ .reg .u64 t; cvta.to.shared.u64 t, %1; cvt.u32.u64 %0, t; }" : "=r"(a) : "l"(p));
    return a;
}
__device__ __forceinline__ void ldm4(uint32_t* r, uint32_t addr) {
    asm volatile("ldmatrix.sync.aligned.m8n8.x4.shared.b16 {%0,%1,%2,%3}, [%4];"
        : "=r"(r[0]), "=r"(r[1]), "=r"(r[2]), "=r"(r[3]) : "r"(addr));
}
__device__ __forceinline__ void mma16816(float* d, const uint32_t* a, uint32_t b0, uint32_t b1) {
    asm volatile("mma.sync.aligned.m16n8k16.row.col.f32.f16.f16.f32 "
        "{%0,%1,%2,%3}, {%4,%5,%6,%7}, {%8,%9}, {%0,%1,%2,%3};"
        : "+f"(d[0]), "+f"(d[1]), "+f"(d[2]), "+f"(d[3])
        : "r"(a[0]), "r"(a[1]), "r"(a[2]), "r"(a[3]), "r"(b0), "r"(b1));
}
#define CP16(dst, src) \
    asm volatile("cp.async.cg.shared.global [%0], [%1], 16;" :: "r"(dst), "l"(src) : "memory")
#define CPCOMMIT() asm volatile("cp.async.commit_group;" ::: "memory")

// stage: A 64x128B (swizzled) + B 128x128B (swizzled)
#define A_T     8192
#define B_T     16384
#define STAGE   (A_T + B_T)            // 24576
#define EPI_B   32768                  // 64 x 128 fp32 (permuted)
#define SM128   (2 * STAGE > EPI_B ? 2 * STAGE : EPI_B)   // 49152
#define SM512   (3 * STAGE)                                // 73728

// ---------------------------------------------------------------------------
// Streaming HMMA GEMM (round-8 proven): CTA 64x128, 8 warps 2m x 4n.
// MODE 0: A = g_xh;   epi = +bias -> g_qkv                      (K=128, N=384)
// MODE 1: A = g_attn; epi = unshift + LN1 + residual(x) -> x1h  (K=128, N=128)
// MODE 2: A = g_x1h;  epi = GELU -> g_h                          (K=128, N=512)
// MODE 3: A = g_h;    epi = LN2 + residual(x1h) -> out fp32      (K=512, N=128)
// ---------------------------------------------------------------------------
template<int MODE, int K>
__global__ __launch_bounds__(256, 3)
void tc_gemm(int woff, const float* __restrict__ bias, float* __restrict__ outp,
             const float* __restrict__ xin, const float* __restrict__ gamma,
             const float* __restrict__ beta)
{
    constexpr int NC = K / 64;
    constexpr int STAGES = (NC >= 3) ? 3 : 2;

    extern __shared__ __align__(1024) char smem[];
    const uint32_t sb = smem_u32(smem);
    const int tid = threadIdx.x;
    const int lane = tid & 31;
    const int wid = tid >> 5;
    const int wm = wid & 1;
    const int wn = wid >> 1;
    const int rowBlock = blockIdx.x * 64;
    const int colBlock = blockIdx.y * 128;

    const __half* asrc;
    if (MODE == 0) asrc = g_xh;
    else if (MODE == 1) asrc = g_attn;
    else if (MODE == 2) asrc = g_x1h;
    else asrc = g_h;
    const __half* wsrc = g_w + woff;

    const int lcc  = tid & 7;
    const int lrow = tid >> 3;
    const uint32_t swo = (uint32_t)(lcc ^ (lrow & 7)) * 16;

    float acc[2][4][4];
    #pragma unroll
    for (int mt = 0; mt < 2; mt++)
        #pragma unroll
        for (int nt = 0; nt < 4; nt++)
            #pragma unroll
            for (int e = 0; e < 4; e++) acc[mt][nt][e] = 0.f;

    auto load_stage = [&](int ch, int s) {
        const int k0 = ch * 64 + lcc * 8;
        const uint32_t sA = sb + (uint32_t)s * STAGE;
        #pragma unroll
        for (int j = 0; j < 2; j++) {
            const int row = lrow + 32 * j;
            CP16(sA + (uint32_t)row * 128 + swo, asrc + (size_t)(rowBlock + row) * K + k0);
        }
        #pragma unroll
        for (int j = 0; j < 4; j++) {
            const int row = lrow + 32 * j;
            CP16(sA + A_T + (uint32_t)row * 128 + swo, wsrc + (size_t)(colBlock + row) * K + k0);
        }
        CPCOMMIT();
    };

    const int lmRow = lane & 15;
    const int lmHalf = lane >> 4;

    load_stage(0, 0);
    if (STAGES >= 3 && NC >= 2) load_stage(1, 1);

    for (int ch = 0; ch < NC; ch++) {
        const int nxt = ch + STAGES - 1;
        if (nxt < NC) {
            load_stage(nxt, nxt % STAGES);
            if (STAGES == 3) asm volatile("cp.async.wait_group 2;" ::: "memory");
            else             asm volatile("cp.async.wait_group 1;" ::: "memory");
        } else {
            if (STAGES == 3 && ch < NC - 1) asm volatile("cp.async.wait_group 1;" ::: "memory");
            else                             asm volatile("cp.async.wait_group 0;" ::: "memory");
        }
        __syncthreads();

        const uint32_t sA = sb + (uint32_t)(ch % STAGES) * STAGE;
        const uint32_t sB = sA + A_T;
        #pragma unroll
        for (int kk = 0; kk < 4; kk++) {
            const int chk = kk * 2 + lmHalf;
            uint32_t af[2][4], bf[2][4];
            #pragma unroll
            for (int mt = 0; mt < 2; mt++) {
                const int rA = wm * 32 + mt * 16 + lmRow;
                ldm4(af[mt], sA + (uint32_t)rA * 128 + (uint32_t)((chk ^ (rA & 7)) * 16));
            }
            #pragma unroll
            for (int pt = 0; pt < 2; pt++) {
                const int rB = wn * 32 + pt * 16 + lmRow;
                ldm4(bf[pt], sB + (uint32_t)rB * 128 + (uint32_t)((chk ^ (rB & 7)) * 16));
            }
            #pragma unroll
            for (int mt = 0; mt < 2; mt++)
                #pragma unroll
                for (int nt = 0; nt < 4; nt++)
                    mma16816(acc[mt][nt], af[mt], bf[nt >> 1][nt & 1], bf[nt >> 1][(nt & 1) + 2]);
        }
        __syncthreads();
    }

    if (MODE == 0 || MODE == 2) {
        const int ld = (MODE == 0) ? 384 : 512;
        __half* base = (MODE == 0) ? g_qkv : g_h;
        #pragma unroll
        for (int mt = 0; mt < 2; mt++) {
            const int r0 = rowBlock + wm * 32 + mt * 16 + (lane >> 2);
            #pragma unroll
            for (int nt = 0; nt < 4; nt++) {
                const int c = colBlock + wn * 32 + nt * 8 + (lane & 3) * 2;
                const float b0 = bias[c], b1 = bias[c + 1];
                #pragma unroll
                for (int hh = 0; hh < 2; hh++) {
                    const int r = r0 + hh * 8;
                    float v0 = acc[mt][nt][hh * 2 + 0] + b0;
                    float v1 = acc[mt][nt][hh * 2 + 1] + b1;
                    if (MODE == 2) { v0 *= normcdff(v0); v1 *= normcdff(v1); }
                    *(__half2*)(base + (size_t)r * ld + c) = __floats2half2_rn(v0, v1);
                }
            }
        }
        return;
    }

    // LN modes (1 and 3): permuted fp32 staging + warp-per-row epilogue
    float* sf = (float*)smem;
    #pragma unroll
    for (int mt = 0; mt < 2; mt++) {
        #pragma unroll
        for (int nt = 0; nt < 4; nt++) {
            const int r0 = wm * 32 + mt * 16 + (lane >> 2);
            const int c  = wn * 32 + nt * 8 + (lane & 3) * 2;
            const int p0 = (c + 8 * r0) & 127;
            *(float2*)(sf + r0 * 128 + p0) = make_float2(acc[mt][nt][0], acc[mt][nt][1]);
            const int r1 = r0 + 8;
            const int p1 = (c + 8 * r1) & 127;
            *(float2*)(sf + r1 * 128 + p1) = make_float2(acc[mt][nt][2], acc[mt][nt][3]);
        }
    }
    __syncthreads();

    #pragma unroll 1
    for (int rr = 0; rr < 8; rr++) {
        const int lr = wid * 8 + rr;
        const int r  = rowBlock + lr;
        float4 v = *(float4*)(sf + lr * 128 + lane * 4);
        const int col = (lane * 4 - lr * 8) & 127;
        const float4 bv = *(const float4*)(bias + col);
        v.x += bv.x; v.y += bv.y; v.z += bv.z; v.w += bv.w;

        float s  = v.x + v.y + v.z + v.w;
        float s2 = v.x * v.x + v.y * v.y + v.z * v.z + v.w * v.w;
        #pragma unroll
        for (int off = 16; off > 0; off >>= 1) {
            s  += __shfl_xor_sync(0xFFFFFFFFu, s,  off);
            s2 += __shfl_xor_sync(0xFFFFFFFFu, s2, off);
        }
        const float mean = s * (1.f / 128.f);
        const float var  = fmaxf(s2 * (1.f / 128.f) - mean * mean, 0.f);
        const float rstd = rsqrtf(var + 1e-5f);

        const float4 gv = *(const float4*)(gamma + col);
        const float4 be = *(const float4*)(beta + col);

        int b = r / (NNH * LL), rem = r % (NNH * LL);
        int n = rem / LL, li = rem % LL;

        if (MODE == 1) {
            int lo_ = li - SHIFTSZ; if (lo_ < 0) lo_ += LL;
            const float4 res = *(const float4*)(xin + ((size_t)(b * LL + lo_) * NNH + n) * DDIM + col);
            float y0 = (v.x - mean) * rstd * gv.x + be.x + res.x;
            float y1 = (v.y - mean) * rstd * gv.y + be.y + res.y;
            float y2 = (v.z - mean) * rstd * gv.z + be.z + res.z;
            float y3 = (v.w - mean) * rstd * gv.w + be.w + res.w;
            __align__(8) __half hv[4];
            hv[0] = __float2half_rn(y0); hv[1] = __float2half_rn(y1);
            hv[2] = __float2half_rn(y2); hv[3] = __float2half_rn(y3);
            *(uint2*)(g_x1h + ((size_t)(b * NNH + n) * LL + lo_) * DDIM + col) = *(uint2*)hv;
        } else {
            const uint2 rh = *(const uint2*)(g_x1h + (size_t)r * 128 + col);
            const __half* rp = (const __half*)&rh;
            float4 o;
            o.x = (v.x - mean) * rstd * gv.x + be.x + __half2float(rp[0]);
            o.y = (v.y - mean) * rstd * gv.y + be.y + __half2float(rp[1]);
            o.z = (v.z - mean) * rstd * gv.z + be.z + __half2float(rp[2]);
            o.w = (v.w - mean) * rstd * gv.w + be.w + __half2float(rp[3]);
            *(float4*)(outp + ((size_t)(b * LL + li) * NNH + n) * DDIM + col) = o;
        }
    }
}

// ---------------------------------------------------------------------------
// prep_x: x (B,L,N,D fp32) -> g_xh (b,n,ls) fp16 with shift fused.
// ---------------------------------------------------------------------------
__global__ __launch_bounds__(256)
void prep_x(const float* __restrict__ x)
{
    const int row = blockIdx.x * 8 + (threadIdx.x >> 5);
    const int lane = threadIdx.x & 31;
    int b = row / (NNH * LL), rem = row % (NNH * LL);
    int n = rem / LL, ls = rem % LL;
    int l = ls - SHIFTSZ; if (l < 0) l += LL;
    const float4 v = *(const float4*)(x + ((size_t)(b * LL + l) * NNH + n) * DDIM + lane * 4);
    __align__(8) __half hv[4];
    hv[0] = __float2half_rn(v.x); hv[1] = __float2half_rn(v.y);
    hv[2] = __float2half_rn(v.z); hv[3] = __float2half_rn(v.w);
    *(uint2*)(g_xh + (size_t)row * 128 + lane * 4) = *(uint2*)hv;
}

// ---------------------------------------------------------------------------
// Weight prep: fp32 [K][N] -> transposed fp16 [N][K]
// ---------------------------------------------------------------------------
__global__ void prep_w(const float* __restrict__ qkv_w, const float* __restrict__ proj_w,
                       const float* __restrict__ fc1_w, const float* __restrict__ fc2_w)
{
    int idx = blockIdx.x * 256 + threadIdx.x;
    if (idx >= W_TOTAL) return;
    const float* src; int K, N, base;
    if (idx < OFF_PROJ)      { src = qkv_w;  K = 128; N = 384; base = OFF_QKV;  }
    else if (idx < OFF_FC1)  { src = proj_w; K = 128; N = 128; base = OFF_PROJ; }
    else if (idx < OFF_FC2)  { src = fc1_w;  K = 128; N = 512; base = OFF_FC1;  }
    else                     { src = fc2_w;  K = 512; N = 128; base = OFF_FC2;  }
    int local = idx - base;
    int nn = local / K, kk = local % K;
    g_w[idx] = __float2half_rn(src[(size_t)kk * N + nn]);
}

// ---------------------------------------------------------------------------
// Windowed attention: 192 threads = 4 windows x 48 threads (8 heads x 6
// row-pairs). fp16 smem; each k/v fragment loaded+converted ONCE per 2 rows.
// 4 adjacent windows are contiguous in g_qkv -> one contiguous uint4 stage.
// ---------------------------------------------------------------------------
__global__ __launch_bounds__(192)
void attn_kernel()
{
    __shared__ __half s[4][12 * 384];   // 36 KB

    const int blk = blockIdx.x;
    const int wp  = blk % (NWIN / 4);   // 6 window-quads
    const int rem = blk / (NWIN / 4);
    const int n   = rem % NNH;
    const int b   = rem / NNH;
    const int tid = threadIdx.x;

    // stage: 4 windows x 576 uint4 = 2304 uint4, fully contiguous in g_qkv
    const size_t qbase = ((size_t)(b * NNH + n) * LL + wp * 48) * 384;
    {
        const uint4* src = (const uint4*)(g_qkv + qbase);
        uint4* dst = (uint4*)(&s[0][0]);
        #pragma unroll
        for (int v = 0; v < 12; v++)
            dst[tid + v * 192] = src[tid + v * 192];
    }
    __syncthreads();

    const int win = tid / 48;           // window within quad
    const int t   = tid % 48;
    const int h   = t / 6;              // head
    const int rp  = t % 6;              // row-pair: rows 2rp, 2rp+1
    const int i0  = rp * 2;
    const int i1  = i0 + 1;
    const int w   = wp * 4 + win;
    const __half* sp = s[win];
    const bool gi = (i0 < SHIFTSZ);     // i0,i1 never straddle (6 even)
    const bool masked = (w == 0);

    // q for both rows -> fp32 registers
    float q0[16], q1[16];
    #pragma unroll
    for (int e = 0; e < 2; e++) {
        uint4 a = *(const uint4*)(sp + i0 * 384 + h * 16 + e * 8);
        uint4 c = *(const uint4*)(sp + i1 * 384 + h * 16 + e * 8);
        const __half2* pa = (const __half2*)&a;
        const __half2* pc = (const __half2*)&c;
        #pragma unroll
        for (int u = 0; u < 4; u++) {
            float2 fa = __half22float2(pa[u]);
            float2 fc = __half22float2(pc[u]);
            q0[e * 8 + u * 2] = fa.x; q0[e * 8 + u * 2 + 1] = fa.y;
            q1[e * 8 + u * 2] = fc.x; q1[e * 8 + u * 2 + 1] = fc.y;
        }
    }

    float sc0[12], sc1[12];
    float mx0 = -1e30f, mx1 = -1e30f;
    #pragma unroll
    for (int j = 0; j < 12; j++) {
        // load k[j] once, convert once, dot with both q rows
        uint4 ka = *(const uint4*)(sp + j * 384 + 128 + h * 16);
        uint4 kb = *(const uint4*)(sp + j * 384 + 128 + h * 16 + 8);
        const __half2* pa = (const __half2*)&ka;
        const __half2* pb = (const __half2*)&kb;
        float a0 = 0.f, a1 = 0.f;
        #pragma unroll
        for (int u = 0; u < 4; u++) {
            float2 fa = __half22float2(pa[u]);
            float2 fb = __half22float2(pb[u]);
            a0 += q0[u * 2] * fa.x + q0[u * 2 + 1] * fa.y
                + q0[8 + u * 2] * fb.x + q0[8 + u * 2 + 1] * fb.y;
            a1 += q1[u * 2] * fa.x + q1[u * 2 + 1] * fa.y
                + q1[8 + u * 2] * fb.x + q1[8 + u * 2 + 1] * fb.y;
        }
        a0 *= 0.25f; a1 *= 0.25f;
        if (masked && (gi != (j < SHIFTSZ))) { a0 -= 100.f; a1 -= 100.f; }
        sc0[j] = a0; mx0 = fmaxf(mx0, a0);
        sc1[j] = a1; mx1 = fmaxf(mx1, a1);
    }
    float den0 = 0.f, den1 = 0.f;
    #pragma unroll
    for (int j = 0; j < 12; j++) {
        sc0[j] = __expf(sc0[j] - mx0); den0 += sc0[j];
        sc1[j] = __expf(sc1[j] - mx1); den1 += sc1[j];
    }
    const float inv0 = 1.f / den0;
    const float inv1 = 1.f / den1;

    float o0[16], o1[16];
    #pragma unroll
    for (int d = 0; d < 16; d++) { o0[d] = 0.f; o1[d] = 0.f; }
    #pragma unroll
    for (int j = 0; j < 12; j++) {
        const float p0 = sc0[j] * inv0;
        const float p1 = sc1[j] * inv1;
        uint4 va = *(const uint4*)(sp + j * 384 + 256 + h * 16);
        uint4 vb = *(const uint4*)(sp + j * 384 + 256 + h * 16 + 8);
        const __half2* pa = (const __half2*)&va;
        const __half2* pb = (const __half2*)&vb;
        #pragma unroll
        for (int u = 0; u < 4; u++) {
            float2 fa = __half22float2(pa[u]);
            float2 fb = __half22float2(pb[u]);
            o0[u * 2] += p0 * fa.x;     o0[u * 2 + 1] += p0 * fa.y;
            o0[8 + u * 2] += p0 * fb.x; o0[8 + u * 2 + 1] += p0 * fb.y;
            o1[u * 2] += p1 * fa.x;     o1[u * 2 + 1] += p1 * fa.y;
            o1[8 + u * 2] += p1 * fb.x; o1[8 + u * 2 + 1] += p1 * fb.y;
        }
    }

    const size_t rowbase = (size_t)(b * NNH + n) * LL + (size_t)w * WSZ;
    __align__(16) __half hv[16];
    #pragma unroll
    for (int d = 0; d < 8; d++)
        *(__half2*)(hv + d * 2) = __floats2half2_rn(o0[d * 2], o0[d * 2 + 1]);
    __half* d0 = g_attn + (rowbase + i0) * 128 + h * 16;
    *(uint4*)(d0)     = *(uint4*)(hv);
    *(uint4*)(d0 + 8) = *(uint4*)(hv + 8);
    #pragma unroll
    for (int d = 0; d < 8; d++)
        *(__half2*)(hv + d * 2) = __floats2half2_rn(o1[d * 2], o1[d * 2 + 1]);
    __half* d1 = g_attn + (rowbase + i1) * 128 + h * 16;
    *(uint4*)(d1)     = *(uint4*)(hv);
    *(uint4*)(d1 + 8) = *(uint4*)(hv + 8);
}

// ---------------------------------------------------------------------------
extern "C" void kernel_launch(void* const* d_in, const int* in_sizes, int n_in,
                              void* d_out, int out_size)
{
    const float* x      = (const float*)d_in[0];
    const float* qkv_w  = (const float*)d_in[1];
    const float* qkv_b  = (const float*)d_in[2];
    const float* proj_w = (const float*)d_in[3];
    const float* proj_b = (const float*)d_in[4];
    const float* fc1_w  = (const float*)d_in[5];
    const float* fc1_b  = (const float*)d_in[6];
    const float* fc2_w  = (const float*)d_in[7];
    const float* fc2_b  = (const float*)d_in[8];
    const float* g1     = (const float*)d_in[9];
    const float* b1     = (const float*)d_in[10];
    const float* g2     = (const float*)d_in[11];
    const float* b2     = (const float*)d_in[12];
    float* out = (float*)d_out;

    static bool attr_done = false;
    if (!attr_done) {
        cudaFuncSetAttribute(tc_gemm<0, 128>, cudaFuncAttributeMaxDynamicSharedMemorySize, SM128);
        cudaFuncSetAttribute(tc_gemm<1, 128>, cudaFuncAttributeMaxDynamicSharedMemorySize, SM128);
        cudaFuncSetAttribute(tc_gemm<2, 128>, cudaFuncAttributeMaxDynamicSharedMemorySize, SM128);
        cudaFuncSetAttribute(tc_gemm<3, 512>, cudaFuncAttributeMaxDynamicSharedMemorySize, SM512);
        attr_done = true;
    }

    const int MB = MTOK / 64; // 3060

    // 0) weight transpose to fp16 [N][K]; x gather/shift to fp16
    prep_w<<<(W_TOTAL + 255) / 256, 256>>>(qkv_w, proj_w, fc1_w, fc2_w);
    prep_x<<<MTOK / 8, 256>>>(x);
    // 1) QKV projection (streaming, 3 column blocks)
    tc_gemm<0, 128><<<dim3(MB, 3), 256, SM128>>>(OFF_QKV, qkv_b, nullptr, nullptr, nullptr, nullptr);
    // 2) windowed attention (4 windows per block, fp16 smem, row-pair reuse)
    attn_kernel<<<BB * NNH * (NWIN / 4), 192>>>();
    // 3) proj + unshift + LN1 + residual(x)
    tc_gemm<1, 128><<<dim3(MB, 1), 256, SM128>>>(OFF_PROJ, proj_b, nullptr, x, g1, b1);
    // 4) fc1 + GELU
    tc_gemm<2, 128><<<dim3(MB, 4), 256, SM128>>>(OFF_FC1, fc1_b, nullptr, nullptr, nullptr, nullptr);
    // 5) fc2 + LN2 + residual(x1h) + scatter to (B,L,N,D)
    tc_gemm<3, 512><<<dim3(MB, 1), 256, SM512>>>(OFF_FC2, fc2_b, out, nullptr, g2, b2);
}